// round 6
// baseline (speedup 1.0000x reference)
#include <cuda_runtime.h>

// SparseLinear: out[b, c] = sum_l w[b,l] * table[x[b,l], c]
// B=4096, L=200, C=128, table = 1,000,000 x 128 fp32 (512 MB).
//
// Self-paced tile-major decomposition: table split into 4 tiles of 256k rows.
// Grid = (batch, NTILE) with tile on y (slowest bid axis), so consecutive
// launch waves process one tile at a time. A tile's ~141k unique referenced
// rows (~72 MB) fit in L2, so all within-tile repeat gathers hit L2 -- no
// barrier needed (R3's failure mode). Whole-row LDG.128 gather kept from R5.
// Partials go to static scratch; a deterministic reduce kernel sums them.

#define SL_L 200
#define SL_C 128
#define SL_B 4096
#define NTILE 4
#define TILE_SHIFT 18    // tile = idx >> 18  (1e6 rows -> tiles of 262144 rows)

__device__ float g_partial[NTILE * SL_B * SL_C];   // 8 MB static scratch

__global__ __launch_bounds__(SL_C) void sl_gather_partial(
    const int* __restrict__ x,
    const float* __restrict__ w,
    const float* __restrict__ table,
    int batch)
{
    __shared__ int    sx[SL_L];
    __shared__ float  sw[SL_L];
    __shared__ float4 sred[SL_C];

    const int b    = blockIdx.x;       // batch row
    const int tile = blockIdx.y;       // table tile (slow axis -> tile-major waves)
    const int t    = threadIdx.x;
    const int lane = t & 31;           // columns 4*lane..4*lane+3
    const int wg   = t >> 5;           // warp id: l = wg, wg+4, ...

    #pragma unroll
    for (int i = t; i < SL_L; i += SL_C) {
        sx[i] = x[b * SL_L + i];
        sw[i] = w[b * SL_L + i];
    }
    __syncthreads();

    const float4* __restrict__ t4 = (const float4*)table;
    float4 acc = make_float4(0.f, 0.f, 0.f, 0.f);

    // Each warp scans its L-strides, gathers rows belonging to this tile.
    #pragma unroll 5
    for (int l = wg; l < SL_L; l += 4) {
        const int idx = sx[l];
        if ((idx >> TILE_SHIFT) == tile) {
            const unsigned o = (unsigned)idx * 32u + (unsigned)lane;
            const float  wv = sw[l];
            const float4 v  = __ldg(t4 + o);
            acc.x += wv * v.x;
            acc.y += wv * v.y;
            acc.z += wv * v.z;
            acc.w += wv * v.w;
        }
    }

    // 4-way cross-warp reduce; warp 0 writes the partial row.
    sred[t] = acc;
    __syncthreads();

    if (wg == 0) {
        float4 a0 = sred[lane];
        float4 a1 = sred[lane + 32];
        float4 a2 = sred[lane + 64];
        float4 a3 = sred[lane + 96];
        float4 r;
        r.x = (a0.x + a1.x) + (a2.x + a3.x);
        r.y = (a0.y + a1.y) + (a2.y + a3.y);
        r.z = (a0.z + a1.z) + (a2.z + a3.z);
        r.w = (a0.w + a1.w) + (a2.w + a3.w);
        ((float4*)g_partial)[(tile * batch + b) * 32 + lane] = r;
    }
}

__global__ __launch_bounds__(SL_C) void sl_reduce(
    float* __restrict__ out, int batch)
{
    const int b = blockIdx.x;
    const int t = threadIdx.x;
    const int base = b * SL_C + t;
    float s = g_partial[base];
    #pragma unroll
    for (int tile = 1; tile < NTILE; ++tile)
        s += g_partial[tile * batch * SL_C + base];
    out[base] = s;
}

extern "C" void kernel_launch(void* const* d_in, const int* in_sizes, int n_in,
                              void* d_out, int out_size)
{
    const int*   x     = (const int*)d_in[0];
    const float* w     = (const float*)d_in[1];
    const float* table = (const float*)d_in[2];
    float*       out   = (float*)d_out;

    int batch = out_size / SL_C;     // 4096
    if (batch <= 0) batch = SL_B;

    dim3 grid(batch, NTILE);
    sl_gather_partial<<<grid, SL_C>>>(x, w, table, batch);
    sl_reduce<<<batch, SL_C>>>(out, batch);
}

// round 7
// speedup vs baseline: 1.2162x; 1.2162x over previous
#include <cuda_runtime.h>

// SparseLinear: out[b, c] = sum_l w[b,l] * table[x[b,l], c]
// B=4096, L=200, C=128, table = 1,000,000 x 128 fp32 (512 MB).
//
// Synchronized global sweep: grid = 2048 CTAs (single co-resident wave), each
// CTA owns 2 batch rows and counting-sorts their 400 (idx,row,w) entries
// jointly by table address. All CTAs start together and sweep the table in
// ascending address order; position spread ~1/sqrt(400) keeps every CTA
// inside a ~50 MB moving window, so cross-CTA repeat gathers hit L2.
// Whole-row LDG.128 gather (one warp = one 512 B row) kept from R5.

#define SL_L   200
#define SL_C   128
#define NPAIR  2                 // batch rows per CTA
#define NL     (SL_L * NPAIR)    // 400 jointly sorted entries
#define NBKT   64
#define KEY_SHIFT 15             // bucket = key >> 15 == idx >> 14

__global__ __launch_bounds__(SL_C, 14) void sparse_linear_kernel(
    const int* __restrict__ x,
    const float* __restrict__ w,
    const float* __restrict__ table,
    float* __restrict__ out,
    int batch)
{
    __shared__ int    sx[NL];         // staging: packed keys
    __shared__ float  sw[NL];
    __shared__ int    sx2[NL];        // address-sorted keys
    __shared__ float  sw2[NL];
    __shared__ int    off[NBKT];
    __shared__ float4 sred0[SL_C];    // reduction buffers (one per row)
    __shared__ float4 sred1[SL_C];

    const int g    = blockIdx.x;
    const int t    = threadIdx.x;
    const int lane = t & 31;          // columns 4*lane..4*lane+3
    const int wg   = t >> 5;          // warp id: entries l = wg, wg+4, ...

    const int b0 = 2 * g;             // two contiguous batch rows
    const int b1 = 2 * g + 1;
    const bool has1 = (b1 < batch);

    if (t < NBKT) off[t] = 0;

    // Stage 400 contiguous (x, w) and pack key = idx*2 + row.
    #pragma unroll
    for (int i = t; i < NL; i += SL_C) {
        int src = b0 * SL_L + i;                 // rows 2g, 2g+1 are contiguous
        int row = (i >= SL_L) ? 1 : 0;
        int idx = (row && !has1) ? 0 : x[src];   // pad row -> idx 0, weight 0
        float wv = (row && !has1) ? 0.0f : w[src];
        sx[i] = idx * 2 + row;
        sw[i] = wv;
    }
    __syncthreads();

    // Histogram by table-address bits.
    #pragma unroll
    for (int i = t; i < NL; i += SL_C)
        atomicAdd(&off[sx[i] >> KEY_SHIFT], 1);
    __syncthreads();

    // Exclusive prefix over 64 counts (warp 0).
    if (t < 32) {
        const unsigned FULL = 0xffffffffu;
        int c0 = off[t], c1 = off[t + 32];
        int s0 = c0, s1 = c1;
        #pragma unroll
        for (int d = 1; d < 32; d <<= 1) {
            int n0 = __shfl_up_sync(FULL, s0, d);
            int n1 = __shfl_up_sync(FULL, s1, d);
            if (t >= d) { s0 += n0; s1 += n1; }
        }
        int tot0 = __shfl_sync(FULL, s0, 31);
        off[t]      = s0 - c0;
        off[t + 32] = tot0 + s1 - c1;
    }
    __syncthreads();

    // Scatter into address-sorted order.
    #pragma unroll
    for (int i = t; i < NL; i += SL_C) {
        int   key = sx[i];
        float wv  = sw[i];
        int p = atomicAdd(&off[key >> KEY_SHIFT], 1);
        sx2[p] = key;
        sw2[p] = wv;
    }
    __syncthreads();

    // Gather: warp wg covers entries l = wg, wg+4, ... (100 each), one
    // LDG.128 per entry. Row select via two FSELs (no branches).
    const float4* __restrict__ t4 = (const float4*)table;
    float4 acc0 = make_float4(0.f, 0.f, 0.f, 0.f);
    float4 acc1 = make_float4(0.f, 0.f, 0.f, 0.f);

    #pragma unroll 5
    for (int l = wg; l < NL; l += 4) {
        const int   key = sx2[l];
        const float wv  = sw2[l];
        const unsigned o = (unsigned)(key >> 1) * 32u + (unsigned)lane;
        const float4 v  = __ldg(t4 + o);
        const float w0 = (key & 1) ? 0.0f : wv;
        const float w1 = (key & 1) ? wv   : 0.0f;
        acc0.x += w0 * v.x;  acc0.y += w0 * v.y;
        acc0.z += w0 * v.z;  acc0.w += w0 * v.w;
        acc1.x += w1 * v.x;  acc1.y += w1 * v.y;
        acc1.z += w1 * v.z;  acc1.w += w1 * v.w;
    }

    // Cross-warp reduce both rows; warps 0/1 store rows b0/b1.
    sred0[t] = acc0;
    sred1[t] = acc1;
    __syncthreads();

    if (wg == 0) {
        float4 a0 = sred0[lane];
        float4 a1 = sred0[lane + 32];
        float4 a2 = sred0[lane + 64];
        float4 a3 = sred0[lane + 96];
        float4 r;
        r.x = (a0.x + a1.x) + (a2.x + a3.x);
        r.y = (a0.y + a1.y) + (a2.y + a3.y);
        r.z = (a0.z + a1.z) + (a2.z + a3.z);
        r.w = (a0.w + a1.w) + (a2.w + a3.w);
        ((float4*)out)[b0 * 32 + lane] = r;
    } else if (wg == 1 && has1) {
        float4 a0 = sred1[lane];
        float4 a1 = sred1[lane + 32];
        float4 a2 = sred1[lane + 64];
        float4 a3 = sred1[lane + 96];
        float4 r;
        r.x = (a0.x + a1.x) + (a2.x + a3.x);
        r.y = (a0.y + a1.y) + (a2.y + a3.y);
        r.z = (a0.z + a1.z) + (a2.z + a3.z);
        r.w = (a0.w + a1.w) + (a2.w + a3.w);
        ((float4*)out)[b1 * 32 + lane] = r;
    }
}

extern "C" void kernel_launch(void* const* d_in, const int* in_sizes, int n_in,
                              void* d_out, int out_size)
{
    const int*   x     = (const int*)d_in[0];
    const float* w     = (const float*)d_in[1];
    const float* table = (const float*)d_in[2];
    float*       out   = (float*)d_out;

    int batch = out_size / SL_C;     // 4096
    if (batch <= 0) batch = 4096;

    int grid = (batch + NPAIR - 1) / NPAIR;   // 2048: single co-resident wave
    sparse_linear_kernel<<<grid, SL_C>>>(x, w, table, out, batch);
}

// round 8
// speedup vs baseline: 1.2460x; 1.0245x over previous
#include <cuda_runtime.h>

// SparseLinear: out[b, c] = sum_l w[b,l] * table[x[b,l], c]
// B=4096, L=200, C=128, table = 1,000,000 x 128 fp32 (512 MB).
//
// Single-wave synchronized sweep (R7) with a register-staged sort:
// grid = 2048 co-resident CTAs, each owns 2 batch rows; the 400 (idx,row,w)
// entries are counting-sorted by table address so all CTAs sweep the table
// in lockstep -> all repeat gathers hit L2 (measured at the ~296 MB byte
// floor). This round removes the exposed sort overhead: entries are staged
// in registers (2x LDG.128 per thread for t<100), histogram + scatter run
// straight from registers, and the sorted array holds fused (key, w) int2
// pairs so the gather loop does a single LDS.64 per entry.

#define SL_L   200
#define SL_C   128
#define NPAIR  2
#define NL     (SL_L * NPAIR)    // 400
#define NBKT   64
#define KEY_SHIFT 15             // bucket = key >> 15 == idx >> 14

__global__ __launch_bounds__(SL_C, 14) void sparse_linear_kernel(
    const int* __restrict__ x,
    const float* __restrict__ w,
    const float* __restrict__ table,
    float* __restrict__ out,
    int batch)
{
    __shared__ int2   sp[NL];         // sorted (key, w-bits) pairs
    __shared__ int    off[NBKT];
    __shared__ float4 sred0[SL_C];
    __shared__ float4 sred1[SL_C];

    const int g    = blockIdx.x;
    const int t    = threadIdx.x;
    const int lane = t & 31;          // columns 4*lane..4*lane+3
    const int wg   = t >> 5;          // warp id: entries l = wg, wg+4, ...

    const int b0 = 2 * g;
    const int b1 = 2 * g + 1;
    const bool has1 = (b1 < batch);

    if (t < NBKT) off[t] = 0;

    // Register staging: thread t<100 owns entries 4t..4t+3.
    // Entries 0..199 are row b0 (t<50), 200..399 are row b1 (t>=50);
    // x rows b0,b1 are contiguous, so one vectorized stream covers both.
    int   k0 = 0, k1 = 0, k2 = 0, k3 = 0;
    float w0 = 0.f, w1 = 0.f, w2 = 0.f, w3 = 0.f;
    bool  active = (t < 100);

    if (active) {
        const int row = (t >= 50) ? 1 : 0;
        if (!row || has1) {
            const int4   xi = __ldg((const int4*)  (x + b0 * SL_L) + t);
            const float4 wi = __ldg((const float4*)(w + b0 * SL_L) + t);
            k0 = xi.x * 2 + row;  w0 = wi.x;
            k1 = xi.y * 2 + row;  w1 = wi.y;
            k2 = xi.z * 2 + row;  w2 = wi.z;
            k3 = xi.w * 2 + row;  w3 = wi.w;
        } else {
            k0 = k1 = k2 = k3 = 1;    // pad row -> idx 0, weight 0
        }
    }
    __syncthreads();

    // Histogram from registers.
    if (active) {
        atomicAdd(&off[k0 >> KEY_SHIFT], 1);
        atomicAdd(&off[k1 >> KEY_SHIFT], 1);
        atomicAdd(&off[k2 >> KEY_SHIFT], 1);
        atomicAdd(&off[k3 >> KEY_SHIFT], 1);
    }
    __syncthreads();

    // Exclusive prefix over 64 counts (warp 0).
    if (t < 32) {
        const unsigned FULL = 0xffffffffu;
        int c0 = off[t], c1 = off[t + 32];
        int s0 = c0, s1 = c1;
        #pragma unroll
        for (int d = 1; d < 32; d <<= 1) {
            int n0 = __shfl_up_sync(FULL, s0, d);
            int n1 = __shfl_up_sync(FULL, s1, d);
            if (t >= d) { s0 += n0; s1 += n1; }
        }
        int tot0 = __shfl_sync(FULL, s0, 31);
        off[t]      = s0 - c0;
        off[t + 32] = tot0 + s1 - c1;
    }
    __syncthreads();

    // Scatter fused (key, w) pairs from registers.
    if (active) {
        int p;
        p = atomicAdd(&off[k0 >> KEY_SHIFT], 1);  sp[p] = make_int2(k0, __float_as_int(w0));
        p = atomicAdd(&off[k1 >> KEY_SHIFT], 1);  sp[p] = make_int2(k1, __float_as_int(w1));
        p = atomicAdd(&off[k2 >> KEY_SHIFT], 1);  sp[p] = make_int2(k2, __float_as_int(w2));
        p = atomicAdd(&off[k3 >> KEY_SHIFT], 1);  sp[p] = make_int2(k3, __float_as_int(w3));
    }
    __syncthreads();

    // Gather: warp wg covers entries l = wg, wg+4, ... (100 each), one
    // LDG.128 (whole 512 B table row) per entry; row select via FSELs.
    const float4* __restrict__ t4 = (const float4*)table;
    float4 acc0 = make_float4(0.f, 0.f, 0.f, 0.f);
    float4 acc1 = make_float4(0.f, 0.f, 0.f, 0.f);

    #pragma unroll 5
    for (int l = wg; l < NL; l += 4) {
        const int2  kw = sp[l];
        const float wv = __int_as_float(kw.y);
        const unsigned o = (unsigned)(kw.x >> 1) * 32u + (unsigned)lane;
        const float4 v = __ldg(t4 + o);
        const float wa = (kw.x & 1) ? 0.0f : wv;
        const float wb = (kw.x & 1) ? wv   : 0.0f;
        acc0.x += wa * v.x;  acc0.y += wa * v.y;
        acc0.z += wa * v.z;  acc0.w += wa * v.w;
        acc1.x += wb * v.x;  acc1.y += wb * v.y;
        acc1.z += wb * v.z;  acc1.w += wb * v.w;
    }

    // Cross-warp reduce both rows; warps 0/1 store rows b0/b1.
    sred0[t] = acc0;
    sred1[t] = acc1;
    __syncthreads();

    if (wg == 0) {
        float4 a0 = sred0[lane];
        float4 a1 = sred0[lane + 32];
        float4 a2 = sred0[lane + 64];
        float4 a3 = sred0[lane + 96];
        float4 r;
        r.x = (a0.x + a1.x) + (a2.x + a3.x);
        r.y = (a0.y + a1.y) + (a2.y + a3.y);
        r.z = (a0.z + a1.z) + (a2.z + a3.z);
        r.w = (a0.w + a1.w) + (a2.w + a3.w);
        ((float4*)out)[b0 * 32 + lane] = r;
    } else if (wg == 1 && has1) {
        float4 a0 = sred1[lane];
        float4 a1 = sred1[lane + 32];
        float4 a2 = sred1[lane + 64];
        float4 a3 = sred1[lane + 96];
        float4 r;
        r.x = (a0.x + a1.x) + (a2.x + a3.x);
        r.y = (a0.y + a1.y) + (a2.y + a3.y);
        r.z = (a0.z + a1.z) + (a2.z + a3.z);
        r.w = (a0.w + a1.w) + (a2.w + a3.w);
        ((float4*)out)[b1 * 32 + lane] = r;
    }
}

extern "C" void kernel_launch(void* const* d_in, const int* in_sizes, int n_in,
                              void* d_out, int out_size)
{
    const int*   x     = (const int*)d_in[0];
    const float* w     = (const float*)d_in[1];
    const float* table = (const float*)d_in[2];
    float*       out   = (float*)d_out;

    int batch = out_size / SL_C;     // 4096
    if (batch <= 0) batch = 4096;

    int grid = (batch + NPAIR - 1) / NPAIR;   // 2048: single co-resident wave
    sparse_linear_kernel<<<grid, SL_C>>>(x, w, table, out, batch);
}